// round 8
// baseline (speedup 1.0000x reference)
#include <cuda_runtime.h>
#include <cuda_bf16.h>
#include <math.h>

#define BB 32
#define TT 512
#define DIN 1824
#define HH 512
#define G4 2048
#define KK 30
#define TSTART 28
#define TSTOP 29
#define NEGV (-10000.0f)
#define MTOT (TT*BB)            /* 16384 */

// ------------------------- device scratch -------------------------
__device__ __nv_bfloat16 g_xwb[2][(size_t)MTOT*G4];  // input proj, bf16
__device__ __nv_bfloat16 g_hsb[(size_t)MTOT*2*HH];   // [m][hf|hb] bf16, m=t*B+b
__device__ float g_feats[(size_t)BB*TT*KK];          // [b][t][k]
__device__ __nv_bfloat16 g_xb[(size_t)MTOT*DIN];     // gathered embeddings, bf16
__device__ __nv_bfloat16 g_wb[2][(size_t)DIN*G4];    // W_ih f/b, bf16
__device__ __nv_bfloat16 g_wb2[2][(size_t)HH*G4];    // W_hh f/b, bf16

__device__ __forceinline__ unsigned smaddr(const void* p)
{
    return (unsigned)__cvta_generic_to_shared(p);
}

__device__ __forceinline__ float tanha(float x)
{
    float r;
    asm("tanh.approx.f32 %0, %1;" : "=f"(r) : "f"(x));
    return r;
}

// ------------------------- cast kernels -------------------------
__global__ __launch_bounds__(256) void k_castx(const float* __restrict__ embed,
                                               const int* __restrict__ ids)
{
    size_t idx = (size_t)blockIdx.x * 256 + threadIdx.x;
    if (idx >= (size_t)MTOT * (DIN / 4)) return;
    int m = (int)(idx / (DIN / 4));
    int q = (int)(idx % (DIN / 4));
    int id = ids[(m & 31) * TT + (m >> 5)];
    float4 v = *(const float4*)(embed + (size_t)id * DIN + 4 * q);
    __nv_bfloat162 lo = __floats2bfloat162_rn(v.x, v.y);
    __nv_bfloat162 hi = __floats2bfloat162_rn(v.z, v.w);
    uint2 pk; pk.x = *(unsigned*)&lo; pk.y = *(unsigned*)&hi;
    *(uint2*)(g_xb + (size_t)m * DIN + 4 * q) = pk;
}

#define NW4 ((size_t)DIN*G4/4)
#define NH4 ((size_t)HH*G4/4)

__global__ __launch_bounds__(256) void k_castw(const float* __restrict__ f0,
                                               const float* __restrict__ f1,
                                               const float* __restrict__ f2,
                                               const float* __restrict__ f3)
{
    size_t idx = (size_t)blockIdx.x * 256 + threadIdx.x;
    const float* src; __nv_bfloat16* dst;
    if (idx < NW4)                    { src = f0; dst = g_wb[0]; }
    else if (idx < 2 * NW4)           { src = f1; dst = g_wb[1]; idx -= NW4; }
    else if (idx < 2 * NW4 + NH4)     { src = f2; dst = g_wb2[0]; idx -= 2 * NW4; }
    else if (idx < 2 * NW4 + 2 * NH4) { src = f3; dst = g_wb2[1]; idx -= 2 * NW4 + NH4; }
    else return;
    float4 v = *(const float4*)(src + 4 * idx);
    __nv_bfloat162 lo = __floats2bfloat162_rn(v.x, v.y);
    __nv_bfloat162 hi = __floats2bfloat162_rn(v.z, v.w);
    uint2 pk; pk.x = *(unsigned*)&lo; pk.y = *(unsigned*)&hi;
    *(uint2*)(dst + 4 * idx) = pk;
}

// ------------------------- input GEMM: both dirs, 3-stage cp.async, bf16 out ----------
#define BM 128
#define BN 128
#define BK 32
#define NKT (DIN / BK)   /* 57 */
#define GA_STRIDE (BK + 8)
#define GB_STRIDE (BN + 8)
#define GA_BUF (BM * GA_STRIDE)
#define GB_BUF (BK * GB_STRIDE)
#define GSMEM ((3 * (GA_BUF + GB_BUF)) * 2)

__global__ __launch_bounds__(256) void k_gemm(const float* __restrict__ bf_,
                                              const float* __restrict__ bb_)
{
    extern __shared__ char gsm[];
    __nv_bfloat16* As = (__nv_bfloat16*)gsm;
    __nv_bfloat16* Bs = As + 3 * GA_BUF;

    int dir = blockIdx.x >> 4;
    int n0 = (blockIdx.x & 15) * BN;
    const float* bias = dir ? bb_ : bf_;
    const __nv_bfloat16* A = g_xb;
    const __nv_bfloat16* Bw = g_wb[dir];
    __nv_bfloat16* out = g_xwb[dir];

    int tid = threadIdx.x;
    int wid = tid >> 5;
    int lane = tid & 31;
    int m0 = blockIdx.y * BM;
    int wm = (wid & 3) * 32;
    int wn = (wid >> 2) * 64;

    float acc[2][8][4];
#pragma unroll
    for (int i = 0; i < 2; i++)
#pragma unroll
        for (int j = 0; j < 8; j++)
#pragma unroll
            for (int r = 0; r < 4; r++) acc[i][j][r] = 0.f;

    auto loadAB = [&](int buf, int k0) {
        __nv_bfloat16* Ab = As + buf * GA_BUF;
        __nv_bfloat16* Bb = Bs + buf * GB_BUF;
#pragma unroll
        for (int j = 0; j < 2; j++) {
            int c = tid + j * 256;
            int r = c >> 2, q = c & 3;
            unsigned dst = smaddr(Ab + r * GA_STRIDE + q * 8);
            const __nv_bfloat16* src = A + (size_t)(m0 + r) * DIN + k0 + q * 8;
            asm volatile("cp.async.cg.shared.global [%0], [%1], 16;\n" :: "r"(dst), "l"(src));
        }
#pragma unroll
        for (int j = 0; j < 2; j++) {
            int c = tid + j * 256;
            int r = c >> 4, q = c & 15;
            unsigned dst = smaddr(Bb + r * GB_STRIDE + q * 8);
            const __nv_bfloat16* src = Bw + (size_t)(k0 + r) * G4 + n0 + q * 8;
            asm volatile("cp.async.cg.shared.global [%0], [%1], 16;\n" :: "r"(dst), "l"(src));
        }
    };

    loadAB(0, 0);
    asm volatile("cp.async.commit_group;\n");
    loadAB(1, BK);
    asm volatile("cp.async.commit_group;\n");

    int buf = 0;
    for (int kt = 0; kt < NKT; kt++) {
        asm volatile("cp.async.wait_group 1;\n");
        __syncthreads();
        if (kt + 2 < NKT) {
            int nb = buf + 2; if (nb >= 3) nb -= 3;
            loadAB(nb, (kt + 2) * BK);
        }
        asm volatile("cp.async.commit_group;\n");

        __nv_bfloat16* Ab = As + buf * GA_BUF;
        __nv_bfloat16* Bb = Bs + buf * GB_BUF;
#pragma unroll
        for (int ks = 0; ks < 2; ks++) {
            int k0 = ks * 16;
            unsigned a[2][4];
#pragma unroll
            for (int mi = 0; mi < 2; mi++) {
                unsigned addr = smaddr(Ab + (wm + mi * 16 + (lane & 15)) * GA_STRIDE + k0 + 8 * (lane >> 4));
                asm volatile("ldmatrix.sync.aligned.m8n8.x4.shared.b16 {%0,%1,%2,%3}, [%4];\n"
                             : "=r"(a[mi][0]), "=r"(a[mi][1]), "=r"(a[mi][2]), "=r"(a[mi][3])
                             : "r"(addr));
            }
            unsigned b[4][4];
#pragma unroll
            for (int nj = 0; nj < 4; nj++) {
                unsigned addr = smaddr(Bb + (k0 + (lane & 15)) * GB_STRIDE + wn + nj * 16 + 8 * (lane >> 4));
                asm volatile("ldmatrix.sync.aligned.m8n8.x4.trans.shared.b16 {%0,%1,%2,%3}, [%4];\n"
                             : "=r"(b[nj][0]), "=r"(b[nj][1]), "=r"(b[nj][2]), "=r"(b[nj][3])
                             : "r"(addr));
            }
#pragma unroll
            for (int mi = 0; mi < 2; mi++)
#pragma unroll
                for (int ni = 0; ni < 8; ni++) {
                    unsigned b0 = b[ni >> 1][(ni & 1) * 2];
                    unsigned b1 = b[ni >> 1][(ni & 1) * 2 + 1];
                    asm volatile(
                        "mma.sync.aligned.m16n8k16.row.col.f32.bf16.bf16.f32 "
                        "{%0,%1,%2,%3}, {%4,%5,%6,%7}, {%8,%9}, {%0,%1,%2,%3};\n"
                        : "+f"(acc[mi][ni][0]), "+f"(acc[mi][ni][1]),
                          "+f"(acc[mi][ni][2]), "+f"(acc[mi][ni][3])
                        : "r"(a[mi][0]), "r"(a[mi][1]), "r"(a[mi][2]), "r"(a[mi][3]),
                          "r"(b0), "r"(b1));
                }
        }
        __syncthreads();
        if (++buf == 3) buf = 0;
    }

#pragma unroll
    for (int mi = 0; mi < 2; mi++) {
#pragma unroll
        for (int ni = 0; ni < 8; ni++) {
            int col = n0 + wn + ni * 8 + (lane & 3) * 2;
            float bx = bias[col], by = bias[col + 1];
            int row0 = m0 + wm + mi * 16 + (lane >> 2);
            __nv_bfloat162 v0 = __floats2bfloat162_rn(acc[mi][ni][0] + bx, acc[mi][ni][1] + by);
            __nv_bfloat162 v1 = __floats2bfloat162_rn(acc[mi][ni][2] + bx, acc[mi][ni][3] + by);
            *(__nv_bfloat162*)(out + (size_t)row0 * G4 + col) = v0;
            *(__nv_bfloat162*)(out + (size_t)(row0 + 8) * G4 + col) = v1;
        }
    }
}

// --------- LSTM: 2 clusters (one per dir), 2 interleaved batch-group streams ---------
// 16 CTAs/cluster; CTA rank owns 32 h-dims x 4 gates = 128 cols; W slice in SMEM with
// B frags hoisted to regs (16 warps x n8 x K=512, no k-split => no reduce).
// Streams bg0/bg1 alternate: stream A's DSMEM exchange is hidden under stream B's compute.
#define WPAD 136
#define SPAD 520
#define GPAD 136
#define STG_ROW   (SPAD*2)              /* 1040 B */
#define STG_PAR   (16*STG_ROW)          /* 16640 B */
#define OFF_STG   (512*WPAD*2)          /* 139264 */
#define OFF_GATES (OFF_STG + 4*STG_PAR) /* + 66560 */
#define OFF_MBAR  (OFF_GATES + 16*GPAD*4)
#define LSM_BYTES (OFF_MBAR + 64)

__global__ __launch_bounds__(512, 1) __cluster_dims__(16, 1, 1)
void k_lstm3(void)
{
    extern __shared__ char smraw[];
    __nv_bfloat16* Ws = (__nv_bfloat16*)smraw;                  // [512][136]
    float* gates = (float*)(smraw + OFF_GATES);                 // [16][136]

    int tid = threadIdx.x;
    int wid = tid >> 5;
    int lane = tid & 31;
    int dir = blockIdx.x >> 4;
    int rank = blockIdx.x & 15;
    int j0 = rank * 32;

    const __nv_bfloat16* Whh = g_wb2[dir];
    const __nv_bfloat16* xw = g_xwb[dir];

    unsigned sbase = smaddr(smraw);
    unsigned stg0  = sbase + OFF_STG;
    unsigned mbar0 = sbase + OFF_MBAR;

    if (tid == 0) {
#pragma unroll
        for (int i = 0; i < 4; i++)
            asm volatile("mbarrier.init.shared.b64 [%0], 16;" :: "r"(mbar0 + i * 8) : "memory");
    }
    // zero parity-0 staging of both streams
    for (int c = tid; c < STG_PAR / 8; c += 512) {
        ((uint2*)(smraw + OFF_STG))[c] = make_uint2(0, 0);
        ((uint2*)(smraw + OFF_STG + 2 * STG_PAR))[c] = make_uint2(0, 0);
    }
    for (int c = tid; c < 512 * 16; c += 512) {
        int k = c >> 4, ch = c & 15;
        int q = ch >> 2, jb = (ch & 3) * 8;
        uint4 v = *(const uint4*)(Whh + (size_t)k * G4 + q * 512 + j0 + jb);
        *(uint4*)(Ws + k * WPAD + q * 32 + jb) = v;
    }
    __syncthreads();
    asm volatile("barrier.cluster.arrive.aligned;" ::: "memory");
    asm volatile("barrier.cluster.wait.aligned;" ::: "memory");

    int ngc = wid * 8;          // warp's 8 gate-cols within CTA's 128

    // hoist B frags: 32 k16-tiles x 2 regs (n8)
    unsigned bfr[32][2];
#pragma unroll
    for (int kk = 0; kk < 32; kk++) {
        unsigned addr = smaddr(Ws + (kk * 16 + (lane & 15)) * WPAD + ngc);
        asm volatile("ldmatrix.sync.aligned.m8n8.x2.trans.shared.b16 {%0,%1}, [%2];\n"
                     : "=r"(bfr[kk][0]), "=r"(bfr[kk][1]) : "r"(addr));
    }

    // DSMEM store targets: 16B chunk (lane>>3) of row wid, to ranks (lane&7), (lane&7)+8
    unsigned pst[2];
#pragma unroll
    for (int i = 0; i < 2; i++) {
        unsigned tgt = (lane & 7) + 8 * i;
        unsigned r;
        asm("mapa.shared::cluster.u32 %0, %1, %2;" : "=r"(r) : "r"(stg0), "r"(tgt));
        pst[i] = r + (unsigned)(wid * STG_ROW + j0 * 2 + (lane >> 3) * 16);
    }
    unsigned pmbar = 0;
    if (wid == 0 && lane < 16)
        asm("mapa.shared::cluster.u32 %0, %1, %2;" : "=r"(pmbar) : "r"(mbar0), "r"(lane));

    int ph[4] = {0, 0, 0, 0};       // phase per (stream, parity)
    float cst[2] = {0.f, 0.f};      // c-state per stream, thread=(batch wid, dim lane)

    for (int s = 0; s < TT; s++) {
        int p = s & 1;
        int t = dir ? (TT - 1 - s) : s;

        // prefetch xw for both streams
        float xq[2][4];
#pragma unroll
        for (int str = 0; str < 2; str++) {
            const __nv_bfloat16* xrow = xw + (size_t)(t * BB + str * 16 + wid) * G4 + j0 + lane;
            xq[str][0] = __bfloat162float(xrow[0]);
            xq[str][1] = __bfloat162float(xrow[512]);
            xq[str][2] = __bfloat162float(xrow[1024]);
            xq[str][3] = __bfloat162float(xrow[1536]);
        }

#pragma unroll
        for (int str = 0; str < 2; str++) {
            int mi = str * 2 + p;
            if (s) {
                unsigned mb = mbar0 + mi * 8;
                asm volatile(
                    "{\n\t.reg .pred P;\n"
                    "WL%=:\n\t"
                    "mbarrier.try_wait.parity.acquire.cluster.shared::cta.b64 P, [%0], %1, 0x989680;\n\t"
                    "@P bra WD%=;\n\t"
                    "bra WL%=;\n"
                    "WD%=:\n\t}"
                    :: "r"(mb), "r"(ph[mi]) : "memory");
                ph[mi] ^= 1;
            }

            unsigned stgp = stg0 + (unsigned)(str * 2 * STG_PAR + p * STG_PAR);
            float acc[4];
            acc[0] = acc[1] = acc[2] = acc[3] = 0.f;
#pragma unroll
            for (int kk = 0; kk < 32; kk++) {
                unsigned a[4];
                unsigned addr = stgp + (unsigned)((lane & 15) * STG_ROW + kk * 32 + (lane >> 4) * 16);
                asm volatile("ldmatrix.sync.aligned.m8n8.x4.shared.b16 {%0,%1,%2,%3}, [%4];\n"
                             : "=r"(a[0]), "=r"(a[1]), "=r"(a[2]), "=r"(a[3]) : "r"(addr));
                asm volatile(
                    "mma.sync.aligned.m16n8k16.row.col.f32.bf16.bf16.f32 "
                    "{%0,%1,%2,%3}, {%4,%5,%6,%7}, {%8,%9}, {%0,%1,%2,%3};\n"
                    : "+f"(acc[0]), "+f"(acc[1]), "+f"(acc[2]), "+f"(acc[3])
                    : "r"(a[0]), "r"(a[1]), "r"(a[2]), "r"(a[3]),
                      "r"(bfr[kk][0]), "r"(bfr[kk][1]));
            }

            // acc -> gates smem (no reduce needed)
            {
                int r = lane >> 2;
                int cb = ngc + (lane & 3) * 2;
                *(float2*)(gates + r * GPAD + cb)       = make_float2(acc[0], acc[1]);
                *(float2*)(gates + (r + 8) * GPAD + cb) = make_float2(acc[2], acc[3]);
            }
            __syncthreads();

            // gate math: thread -> (batch wid, dim lane)
            float h;
            {
                float gi = gates[wid * GPAD + lane]      + xq[str][0];
                float gf = gates[wid * GPAD + 32 + lane] + xq[str][1];
                float gg = gates[wid * GPAD + 64 + lane] + xq[str][2];
                float go = gates[wid * GPAD + 96 + lane] + xq[str][3];
                float c = cst[str];
                float si = 0.5f * tanha(0.5f * gi) + 0.5f;
                float sf = 0.5f * tanha(0.5f * gf) + 0.5f;
                float so = 0.5f * tanha(0.5f * go) + 0.5f;
                c = sf * c + si * tanha(gg);
                cst[str] = c;
                h = so * tanha(c);
            }
            __nv_bfloat16 hb16 = __float2bfloat16(h);
            g_hsb[(size_t)(t * BB + str * 16 + wid) * (2 * HH) + dir * HH + j0 + lane] = hb16;

            if (s + 1 < TT) {
                // pack 8 h (16B) via 3x shfl.bfly; 2 remote v4 stores
                unsigned hb = (unsigned)(*(unsigned short*)&hb16);
                unsigned o1 = __shfl_xor_sync(0xffffffffu, hb, 1);
                unsigned p32 = (lane & 1) ? ((hb << 16) | o1) : ((o1 << 16) | hb);
                unsigned o2 = __shfl_xor_sync(0xffffffffu, p32, 2);
                unsigned lo = (lane & 2) ? o2 : p32;
                unsigned hi = (lane & 2) ? p32 : o2;
                unsigned lo2 = __shfl_xor_sync(0xffffffffu, lo, 4);
                unsigned hi2 = __shfl_xor_sync(0xffffffffu, hi, 4);
                unsigned r0 = (lane & 4) ? lo2 : lo;
                unsigned r1 = (lane & 4) ? hi2 : hi;
                unsigned r2 = (lane & 4) ? lo : lo2;
                unsigned r3 = (lane & 4) ? hi : hi2;
                unsigned off = (unsigned)(str * 2 * STG_PAR + (p ^ 1) * STG_PAR);
#pragma unroll
                for (int i = 0; i < 2; i++)
                    asm volatile("st.shared::cluster.v4.b32 [%0], {%1,%2,%3,%4};"
                                 :: "r"(pst[i] + off), "r"(r0), "r"(r1), "r"(r2), "r"(r3) : "memory");
                __syncthreads();
                if (wid == 0 && lane < 16)
                    asm volatile("mbarrier.arrive.release.cluster.shared::cluster.b64 _, [%0];"
                                 :: "r"(pmbar + (unsigned)((str * 2 + (p ^ 1)) * 8)) : "memory");
            } else {
                __syncthreads();
            }
        }
    }

    asm volatile("barrier.cluster.arrive.aligned;" ::: "memory");
    asm volatile("barrier.cluster.wait.aligned;" ::: "memory");
}

// ------------------------- tag projection: bf16 mma GEMM -------------------------
#define TBK 64
#define TB_STRIDE 40
#define TA_STRIDE 72
#define TA_BUF (128 * TA_STRIDE)
#define TSMEM ((1024 * TB_STRIDE + 2 * TA_BUF) * 2)

__global__ __launch_bounds__(256) void k_tag(const float* __restrict__ Wtag,
                                             const float* __restrict__ btag)
{
    extern __shared__ char tsm[];
    __nv_bfloat16* Bt = (__nv_bfloat16*)tsm;
    __nv_bfloat16* As = Bt + 1024 * TB_STRIDE;

    int tid = threadIdx.x;
    int wid = tid >> 5;
    int lane = tid & 31;
    int m0 = blockIdx.x * 128;

    for (int idx = tid; idx < 1024 * 32; idx += 256) {
        int k = idx >> 5, n = idx & 31;
        float v = (n < KK) ? Wtag[k * KK + n] : 0.f;
        Bt[k * TB_STRIDE + n] = __float2bfloat16(v);
    }

    auto loadA = [&](int buf, int k0) {
        __nv_bfloat16* Ab = As + buf * TA_BUF;
#pragma unroll
        for (int j = 0; j < 4; j++) {
            int c = tid + j * 256;
            int r = c >> 3, q = c & 7;
            unsigned dst = smaddr(Ab + r * TA_STRIDE + q * 8);
            const __nv_bfloat16* src = g_hsb + (size_t)(m0 + r) * 1024 + k0 + q * 8;
            asm volatile("cp.async.cg.shared.global [%0], [%1], 16;\n" :: "r"(dst), "l"(src));
        }
    };

    loadA(0, 0);
    asm volatile("cp.async.commit_group;\n");
    __syncthreads();

    float acc[4][4];
#pragma unroll
    for (int i = 0; i < 4; i++)
#pragma unroll
        for (int j = 0; j < 4; j++) acc[i][j] = 0.f;

    for (int kt = 0; kt < 1024 / TBK; kt++) {
        int buf = kt & 1;
        if (kt + 1 < 1024 / TBK) {
            loadA(buf ^ 1, (kt + 1) * TBK);
            asm volatile("cp.async.commit_group;\n");
            asm volatile("cp.async.wait_group 1;\n");
        } else {
            asm volatile("cp.async.wait_group 0;\n");
        }
        __syncthreads();
        __nv_bfloat16* Ab = As + buf * TA_BUF;
#pragma unroll
        for (int ks = 0; ks < 4; ks++) {
            int k0 = ks * 16;
            int kabs = kt * TBK + k0;
            unsigned a[4];
            unsigned addr = smaddr(Ab + (wid * 16 + (lane & 15)) * TA_STRIDE + k0 + 8 * (lane >> 4));
            asm volatile("ldmatrix.sync.aligned.m8n8.x4.shared.b16 {%0,%1,%2,%3}, [%4];\n"
                         : "=r"(a[0]), "=r"(a[1]), "=r"(a[2]), "=r"(a[3]) : "r"(addr));
            unsigned b[2][4];
#pragma unroll
            for (int nj = 0; nj < 2; nj++) {
                unsigned baddr = smaddr(Bt + (kabs + (lane & 15)) * TB_STRIDE + nj * 16 + 8 * (lane >> 4));
                asm volatile("ldmatrix.sync.aligned.m8n8.x4.trans.shared.b16 {%0,%1,%2,%3}, [%4];\n"
                             : "=r"(b[nj][0]), "=r"(b[nj][1]), "=r"(b[nj][2]), "=r"(b[nj][3])
                             : "r"(baddr));
            }
#pragma unroll
            for (int ni = 0; ni < 4; ni++) {
                unsigned b0 = b[ni >> 1][(ni & 1) * 2];
                unsigned b1 = b[ni >> 1][(ni & 1) * 2 + 1];
                asm volatile(
                    "mma.sync.aligned.m16n8k16.row.col.f32.bf16.bf16.f32 "
                    "{%0,%1,%2,%3}, {%4,%5,%6,%7}, {%8,%9}, {%0,%1,%2,%3};\n"
                    : "+f"(acc[ni][0]), "+f"(acc[ni][1]), "+f"(acc[ni][2]), "+f"(acc[ni][3])
                    : "r"(a[0]), "r"(a[1]), "r"(a[2]), "r"(a[3]), "r"(b0), "r"(b1));
            }
        }
        __syncthreads();
    }

#pragma unroll
    for (int ni = 0; ni < 4; ni++) {
        int col = ni * 8 + (lane & 3) * 2;
#pragma unroll
        for (int half = 0; half < 2; half++) {
            int m = m0 + wid * 16 + (lane >> 2) + half * 8;
            int b = m & 31, t = m >> 5;
            float* fo = g_feats + ((size_t)b * TT + t) * KK;
            if (col < KK)     fo[col]     = acc[ni][half * 2]     + btag[col];
            if (col + 1 < KK) fo[col + 1] = acc[ni][half * 2 + 1] + btag[col + 1];
        }
    }
}

// ------------------------- CRF NLL (one warp per sentence) -------------------------
__global__ void k_crf(const float* __restrict__ trans, const int* __restrict__ tags,
                      float* __restrict__ out)
{
    int b = blockIdx.x;
    int lane = threadIdx.x;
    float trow[KK];
    int lr = (lane < KK) ? lane : 0;
#pragma unroll
    for (int p = 0; p < KK; p++) trow[p] = trans[lr * KK + p];
    float alpha = (lane == TSTART) ? 0.f : NEGV;
    const float* fb = g_feats + (size_t)b * TT * KK;
    for (int t = 0; t < TT; t++) {
        float emit = (lane < KK) ? fb[t * KK + lane] : 0.f;
        float v[KK];
        float vmax = -1e30f;
#pragma unroll
        for (int p = 0; p < KK; p++) {
            v[p] = __shfl_sync(0xffffffffu, alpha, p) + trow[p];
            vmax = fmaxf(vmax, v[p]);
        }
        float ssum = 0.f;
#pragma unroll
        for (int p = 0; p < KK; p++) ssum += __expf(v[p] - vmax);
        float na = vmax + __logf(ssum) + emit;
        alpha = (lane < KK) ? na : NEGV;
    }
    float v = (lane < KK) ? (alpha + trans[TSTOP * KK + lane]) : -1e30f;
    float m = v;
#pragma unroll
    for (int off = 16; off; off >>= 1) m = fmaxf(m, __shfl_xor_sync(0xffffffffu, m, off));
    float e = (lane < KK) ? __expf(v - m) : 0.f;
#pragma unroll
    for (int off = 16; off; off >>= 1) e += __shfl_xor_sync(0xffffffffu, e, off);
    float logz = m + __logf(e);
    const int* tg = tags + b * TT;
    float gold = 0.f;
    for (int j = lane; j < TT + 1; j += 32) {
        int prev = (j == 0) ? TSTART : tg[j - 1];
        int nxt  = (j < TT) ? tg[j] : TSTOP;
        gold += trans[nxt * KK + prev];
        if (j < TT) gold += fb[j * KK + tg[j]];
    }
#pragma unroll
    for (int off = 16; off; off >>= 1) gold += __shfl_xor_sync(0xffffffffu, gold, off);
    if (lane == 0) out[b] = logz - gold;
}

// ------------------------- launcher -------------------------
extern "C" void kernel_launch(void* const* d_in, const int* in_sizes, int n_in,
                              void* d_out, int out_size)
{
    const int*   ids   = (const int*)  d_in[0];
    const int*   tags  = (const int*)  d_in[1];
    const float* embed = (const float*)d_in[2];
    const float* Wihf  = (const float*)d_in[3];
    const float* Whhf  = (const float*)d_in[4];
    const float* bf    = (const float*)d_in[5];
    const float* Wihb  = (const float*)d_in[6];
    const float* Whhb  = (const float*)d_in[7];
    const float* bb    = (const float*)d_in[8];
    const float* Wtag  = (const float*)d_in[9];
    const float* btag  = (const float*)d_in[10];
    const float* trans = (const float*)d_in[11];
    float* out = (float*)d_out;

    cudaFuncSetAttribute(k_gemm, cudaFuncAttributeMaxDynamicSharedMemorySize, GSMEM);
    cudaFuncSetAttribute(k_tag,  cudaFuncAttributeMaxDynamicSharedMemorySize, TSMEM);
    cudaFuncSetAttribute(k_lstm3, cudaFuncAttributeMaxDynamicSharedMemorySize, LSM_BYTES);
    cudaFuncSetAttribute(k_lstm3, cudaFuncAttributeNonPortableClusterSizeAllowed, 1);

    {
        size_t nx = (size_t)MTOT * (DIN / 4);
        k_castx<<<(unsigned)((nx + 255) / 256), 256>>>(embed, ids);
        size_t nwt = 2 * NW4 + 2 * NH4;
        k_castw<<<(unsigned)((nwt + 255) / 256), 256>>>(Wihf, Wihb, Whhf, Whhb);
    }
    k_gemm<<<dim3(32, MTOT / BM), 256, GSMEM>>>(bf, bb);
    k_lstm3<<<32, 512, LSM_BYTES>>>();
    k_tag<<<MTOT / 128, 256, TSMEM>>>(Wtag, btag);
    k_crf<<<BB, 32>>>(trans, tags, out);
}

// round 9
// speedup vs baseline: 2.3544x; 2.3544x over previous
#include <cuda_runtime.h>
#include <cuda_bf16.h>
#include <math.h>

#define BB 32
#define TT 512
#define DIN 1824
#define HH 512
#define G4 2048
#define KK 30
#define TSTART 28
#define TSTOP 29
#define NEGV (-10000.0f)
#define MTOT (TT*BB)            /* 16384 */

// ------------------------- device scratch -------------------------
__device__ __nv_bfloat16 g_xwb[2][(size_t)MTOT*G4];  // input proj, bf16
__device__ __nv_bfloat16 g_hsb[(size_t)MTOT*2*HH];   // [m][hf|hb] bf16, m=t*B+b
__device__ float g_feats[(size_t)BB*TT*KK];          // [b][t][k]
__device__ __nv_bfloat16 g_xb[(size_t)MTOT*DIN];     // gathered embeddings, bf16
__device__ __nv_bfloat16 g_wb[2][(size_t)DIN*G4];    // W_ih f/b, bf16
__device__ __nv_bfloat16 g_wb2[2][(size_t)HH*G4];    // W_hh f/b, bf16

__device__ __forceinline__ unsigned smaddr(const void* p)
{
    return (unsigned)__cvta_generic_to_shared(p);
}

__device__ __forceinline__ float tanha(float x)
{
    float r;
    asm("tanh.approx.f32 %0, %1;" : "=f"(r) : "f"(x));
    return r;
}

// ------------------------- cast kernels -------------------------
__global__ __launch_bounds__(256) void k_castx(const float* __restrict__ embed,
                                               const int* __restrict__ ids)
{
    size_t idx = (size_t)blockIdx.x * 256 + threadIdx.x;
    if (idx >= (size_t)MTOT * (DIN / 4)) return;
    int m = (int)(idx / (DIN / 4));
    int q = (int)(idx % (DIN / 4));
    int id = ids[(m & 31) * TT + (m >> 5)];
    float4 v = *(const float4*)(embed + (size_t)id * DIN + 4 * q);
    __nv_bfloat162 lo = __floats2bfloat162_rn(v.x, v.y);
    __nv_bfloat162 hi = __floats2bfloat162_rn(v.z, v.w);
    uint2 pk; pk.x = *(unsigned*)&lo; pk.y = *(unsigned*)&hi;
    *(uint2*)(g_xb + (size_t)m * DIN + 4 * q) = pk;
}

#define NW4 ((size_t)DIN*G4/4)
#define NH4 ((size_t)HH*G4/4)

__global__ __launch_bounds__(256) void k_castw(const float* __restrict__ f0,
                                               const float* __restrict__ f1,
                                               const float* __restrict__ f2,
                                               const float* __restrict__ f3)
{
    size_t idx = (size_t)blockIdx.x * 256 + threadIdx.x;
    const float* src; __nv_bfloat16* dst;
    if (idx < NW4)                    { src = f0; dst = g_wb[0]; }
    else if (idx < 2 * NW4)           { src = f1; dst = g_wb[1]; idx -= NW4; }
    else if (idx < 2 * NW4 + NH4)     { src = f2; dst = g_wb2[0]; idx -= 2 * NW4; }
    else if (idx < 2 * NW4 + 2 * NH4) { src = f3; dst = g_wb2[1]; idx -= 2 * NW4 + NH4; }
    else return;
    float4 v = *(const float4*)(src + 4 * idx);
    __nv_bfloat162 lo = __floats2bfloat162_rn(v.x, v.y);
    __nv_bfloat162 hi = __floats2bfloat162_rn(v.z, v.w);
    uint2 pk; pk.x = *(unsigned*)&lo; pk.y = *(unsigned*)&hi;
    *(uint2*)(dst + 4 * idx) = pk;
}

// ------------------------- input GEMM: both dirs, 3-stage cp.async, bf16 out ----------
#define BM 128
#define BN 128
#define BK 32
#define NKT (DIN / BK)   /* 57 */
#define GA_STRIDE (BK + 8)
#define GB_STRIDE (BN + 8)
#define GA_BUF (BM * GA_STRIDE)
#define GB_BUF (BK * GB_STRIDE)
#define GSMEM ((3 * (GA_BUF + GB_BUF)) * 2)

__global__ __launch_bounds__(256) void k_gemm(const float* __restrict__ bf_,
                                              const float* __restrict__ bb_)
{
    extern __shared__ char gsm[];
    __nv_bfloat16* As = (__nv_bfloat16*)gsm;
    __nv_bfloat16* Bs = As + 3 * GA_BUF;

    int dir = blockIdx.x >> 4;
    int n0 = (blockIdx.x & 15) * BN;
    const float* bias = dir ? bb_ : bf_;
    const __nv_bfloat16* A = g_xb;
    const __nv_bfloat16* Bw = g_wb[dir];
    __nv_bfloat16* out = g_xwb[dir];

    int tid = threadIdx.x;
    int wid = tid >> 5;
    int lane = tid & 31;
    int m0 = blockIdx.y * BM;
    int wm = (wid & 3) * 32;
    int wn = (wid >> 2) * 64;

    float acc[2][8][4];
#pragma unroll
    for (int i = 0; i < 2; i++)
#pragma unroll
        for (int j = 0; j < 8; j++)
#pragma unroll
            for (int r = 0; r < 4; r++) acc[i][j][r] = 0.f;

    auto loadAB = [&](int buf, int k0) {
        __nv_bfloat16* Ab = As + buf * GA_BUF;
        __nv_bfloat16* Bb = Bs + buf * GB_BUF;
#pragma unroll
        for (int j = 0; j < 2; j++) {
            int c = tid + j * 256;
            int r = c >> 2, q = c & 3;
            unsigned dst = smaddr(Ab + r * GA_STRIDE + q * 8);
            const __nv_bfloat16* src = A + (size_t)(m0 + r) * DIN + k0 + q * 8;
            asm volatile("cp.async.cg.shared.global [%0], [%1], 16;\n" :: "r"(dst), "l"(src));
        }
#pragma unroll
        for (int j = 0; j < 2; j++) {
            int c = tid + j * 256;
            int r = c >> 4, q = c & 15;
            unsigned dst = smaddr(Bb + r * GB_STRIDE + q * 8);
            const __nv_bfloat16* src = Bw + (size_t)(k0 + r) * G4 + n0 + q * 8;
            asm volatile("cp.async.cg.shared.global [%0], [%1], 16;\n" :: "r"(dst), "l"(src));
        }
    };

    loadAB(0, 0);
    asm volatile("cp.async.commit_group;\n");
    loadAB(1, BK);
    asm volatile("cp.async.commit_group;\n");

    int buf = 0;
    for (int kt = 0; kt < NKT; kt++) {
        asm volatile("cp.async.wait_group 1;\n");
        __syncthreads();
        if (kt + 2 < NKT) {
            int nb = buf + 2; if (nb >= 3) nb -= 3;
            loadAB(nb, (kt + 2) * BK);
        }
        asm volatile("cp.async.commit_group;\n");

        __nv_bfloat16* Ab = As + buf * GA_BUF;
        __nv_bfloat16* Bb = Bs + buf * GB_BUF;
#pragma unroll
        for (int ks = 0; ks < 2; ks++) {
            int k0 = ks * 16;
            unsigned a[2][4];
#pragma unroll
            for (int mi = 0; mi < 2; mi++) {
                unsigned addr = smaddr(Ab + (wm + mi * 16 + (lane & 15)) * GA_STRIDE + k0 + 8 * (lane >> 4));
                asm volatile("ldmatrix.sync.aligned.m8n8.x4.shared.b16 {%0,%1,%2,%3}, [%4];\n"
                             : "=r"(a[mi][0]), "=r"(a[mi][1]), "=r"(a[mi][2]), "=r"(a[mi][3])
                             : "r"(addr));
            }
            unsigned b[4][4];
#pragma unroll
            for (int nj = 0; nj < 4; nj++) {
                unsigned addr = smaddr(Bb + (k0 + (lane & 15)) * GB_STRIDE + wn + nj * 16 + 8 * (lane >> 4));
                asm volatile("ldmatrix.sync.aligned.m8n8.x4.trans.shared.b16 {%0,%1,%2,%3}, [%4];\n"
                             : "=r"(b[nj][0]), "=r"(b[nj][1]), "=r"(b[nj][2]), "=r"(b[nj][3])
                             : "r"(addr));
            }
#pragma unroll
            for (int mi = 0; mi < 2; mi++)
#pragma unroll
                for (int ni = 0; ni < 8; ni++) {
                    unsigned b0 = b[ni >> 1][(ni & 1) * 2];
                    unsigned b1 = b[ni >> 1][(ni & 1) * 2 + 1];
                    asm volatile(
                        "mma.sync.aligned.m16n8k16.row.col.f32.bf16.bf16.f32 "
                        "{%0,%1,%2,%3}, {%4,%5,%6,%7}, {%8,%9}, {%0,%1,%2,%3};\n"
                        : "+f"(acc[mi][ni][0]), "+f"(acc[mi][ni][1]),
                          "+f"(acc[mi][ni][2]), "+f"(acc[mi][ni][3])
                        : "r"(a[mi][0]), "r"(a[mi][1]), "r"(a[mi][2]), "r"(a[mi][3]),
                          "r"(b0), "r"(b1));
                }
        }
        __syncthreads();
        if (++buf == 3) buf = 0;
    }

#pragma unroll
    for (int mi = 0; mi < 2; mi++) {
#pragma unroll
        for (int ni = 0; ni < 8; ni++) {
            int col = n0 + wn + ni * 8 + (lane & 3) * 2;
            float bx = bias[col], by = bias[col + 1];
            int row0 = m0 + wm + mi * 16 + (lane >> 2);
            __nv_bfloat162 v0 = __floats2bfloat162_rn(acc[mi][ni][0] + bx, acc[mi][ni][1] + by);
            __nv_bfloat162 v1 = __floats2bfloat162_rn(acc[mi][ni][2] + bx, acc[mi][ni][3] + by);
            *(__nv_bfloat162*)(out + (size_t)row0 * G4 + col) = v0;
            *(__nv_bfloat162*)(out + (size_t)(row0 + 8) * G4 + col) = v1;
        }
    }
}

// ------------------------- LSTM: 4 clusters x 16 CTAs (R6 config + dual gates) --------
// warps: kh = wid&1 (K half of 256), ng = wid>>1 (n16 group). B frags hoisted to regs.
// kh halves write SEPARATE gates buffers; gate math adds them (no RMW reduce pass).
// c-state in registers. DSMEM all-gather of h, double-buffered, mbarrier-synced.
#define WPAD 136
#define SPAD 520
#define GPAD 136
#define STG_ROW   (SPAD*2)              /* 1040 B */
#define STG_PAR   (16*STG_ROW)          /* 16640 B */
#define OFF_STG   (512*WPAD*2)          /* 139264 */
#define OFF_GATES (OFF_STG + 2*STG_PAR) /* 172544 */
#define OFF_MBAR  (OFF_GATES + 2*16*GPAD*4)
#define LSM_BYTES (OFF_MBAR + 64)

__global__ __launch_bounds__(512, 1) __cluster_dims__(16, 1, 1)
void k_lstm2(void)
{
    extern __shared__ char smraw[];
    __nv_bfloat16* Ws = (__nv_bfloat16*)smraw;                  // [512][136]
    float* gatesA = (float*)(smraw + OFF_GATES);                // [16][136] (kh=0)
    float* gatesB = gatesA + 16 * GPAD;                         // [16][136] (kh=1)

    int tid = threadIdx.x;
    int wid = tid >> 5;
    int lane = tid & 31;
    int cid = blockIdx.x >> 4;
    int rank = blockIdx.x & 15;
    int dir = cid >> 1;
    int bg  = cid & 1;
    int j0  = rank * 32;

    const __nv_bfloat16* Whh = g_wb2[dir];
    const __nv_bfloat16* xw = g_xwb[dir];

    unsigned sbase = smaddr(smraw);
    unsigned stg0  = sbase + OFF_STG;
    unsigned mbar0 = sbase + OFF_MBAR;

    if (tid == 0) {
        asm volatile("mbarrier.init.shared.b64 [%0], 16;" :: "r"(mbar0) : "memory");
        asm volatile("mbarrier.init.shared.b64 [%0], 16;" :: "r"(mbar0 + 8) : "memory");
    }
    for (int c = tid; c < STG_PAR / 8; c += 512)
        ((uint2*)(smraw + OFF_STG))[c] = make_uint2(0, 0);
    for (int c = tid; c < 512 * 16; c += 512) {
        int k = c >> 4, ch = c & 15;
        int q = ch >> 2, jb = (ch & 3) * 8;
        uint4 v = *(const uint4*)(Whh + (size_t)k * G4 + q * 512 + j0 + jb);
        *(uint4*)(Ws + k * WPAD + q * 32 + jb) = v;
    }
    __syncthreads();
    asm volatile("barrier.cluster.arrive.aligned;" ::: "memory");
    asm volatile("barrier.cluster.wait.aligned;" ::: "memory");

    int kh = wid & 1;
    int ng = wid >> 1;
    int kbase = kh * 256;
    int ngc = ng * 16;
    float* gw = kh ? gatesB : gatesA;     // this warp's output buffer

    unsigned bfr[16][4];
#pragma unroll
    for (int kk = 0; kk < 16; kk++) {
        int k0 = kbase + kk * 16;
        unsigned addr = smaddr(Ws + (k0 + (lane & 15)) * WPAD + ngc + 8 * (lane >> 4));
        asm volatile("ldmatrix.sync.aligned.m8n8.x4.trans.shared.b16 {%0,%1,%2,%3}, [%4];\n"
                     : "=r"(bfr[kk][0]), "=r"(bfr[kk][1]), "=r"(bfr[kk][2]), "=r"(bfr[kk][3])
                     : "r"(addr));
    }

    // DSMEM store targets: 16B chunk (lane>>3) of row wid, to ranks (lane&7), (lane&7)+8
    unsigned pst[2];
#pragma unroll
    for (int i = 0; i < 2; i++) {
        unsigned tgt = (lane & 7) + 8 * i;
        unsigned r;
        asm("mapa.shared::cluster.u32 %0, %1, %2;" : "=r"(r) : "r"(stg0), "r"(tgt));
        pst[i] = r + (unsigned)(wid * STG_ROW + j0 * 2 + (lane >> 3) * 16);
    }
    unsigned pmbar = 0;
    if (wid == 0 && lane < 16)
        asm("mapa.shared::cluster.u32 %0, %1, %2;" : "=r"(pmbar) : "r"(mbar0), "r"(lane));

    int ph0 = 0, ph1 = 0;
    float cst = 0.f;                      // c for (batch wid, dim lane)

    for (int s = 0; s < TT; s++) {
        int p = s & 1;
        int t = dir ? (TT - 1 - s) : s;

        const __nv_bfloat16* xrow = xw + (size_t)(t * BB + bg * 16 + wid) * G4 + j0 + lane;
        float xq0 = __bfloat162float(xrow[0]);
        float xq1 = __bfloat162float(xrow[512]);
        float xq2 = __bfloat162float(xrow[1024]);
        float xq3 = __bfloat162float(xrow[1536]);

        if (s) {
            unsigned mb = mbar0 + p * 8;
            int phv = p ? ph1 : ph0;
            asm volatile(
                "{\n\t.reg .pred P;\n"
                "WL%=:\n\t"
                "mbarrier.try_wait.parity.acquire.cluster.shared::cta.b64 P, [%0], %1, 0x989680;\n\t"
                "@P bra WD%=;\n\t"
                "bra WL%=;\n"
                "WD%=:\n\t}"
                :: "r"(mb), "r"(phv) : "memory");
            if (p) ph1 ^= 1; else ph0 ^= 1;
        }

        unsigned stgp = stg0 + (unsigned)(p * STG_PAR);
        float acc[2][4];
#pragma unroll
        for (int i = 0; i < 2; i++)
#pragma unroll
            for (int j = 0; j < 4; j++) acc[i][j] = 0.f;

#pragma unroll
        for (int kk = 0; kk < 16; kk++) {
            int k0 = kbase + kk * 16;
            unsigned a[4];
            unsigned addr = stgp + (unsigned)((lane & 15) * STG_ROW + k0 * 2 + (lane >> 4) * 16);
            asm volatile("ldmatrix.sync.aligned.m8n8.x4.shared.b16 {%0,%1,%2,%3}, [%4];\n"
                         : "=r"(a[0]), "=r"(a[1]), "=r"(a[2]), "=r"(a[3]) : "r"(addr));
#pragma unroll
            for (int nt = 0; nt < 2; nt++) {
                asm volatile(
                    "mma.sync.aligned.m16n8k16.row.col.f32.bf16.bf16.f32 "
                    "{%0,%1,%2,%3}, {%4,%5,%6,%7}, {%8,%9}, {%0,%1,%2,%3};\n"
                    : "+f"(acc[nt][0]), "+f"(acc[nt][1]), "+f"(acc[nt][2]), "+f"(acc[nt][3])
                    : "r"(a[0]), "r"(a[1]), "r"(a[2]), "r"(a[3]),
                      "r"(bfr[kk][nt * 2]), "r"(bfr[kk][nt * 2 + 1]));
            }
        }

        // both k-halves store to their own buffer; single sync; add at gate math
        {
            int r = lane >> 2;
            int cb = ngc + (lane & 3) * 2;
#pragma unroll
            for (int nt = 0; nt < 2; nt++) {
                *(float2*)(gw + r * GPAD + cb + nt * 8)       = make_float2(acc[nt][0], acc[nt][1]);
                *(float2*)(gw + (r + 8) * GPAD + cb + nt * 8) = make_float2(acc[nt][2], acc[nt][3]);
            }
        }
        __syncthreads();

        float h;
        {
            float gi = gatesA[wid * GPAD + lane]      + gatesB[wid * GPAD + lane]      + xq0;
            float gf = gatesA[wid * GPAD + 32 + lane] + gatesB[wid * GPAD + 32 + lane] + xq1;
            float gg = gatesA[wid * GPAD + 64 + lane] + gatesB[wid * GPAD + 64 + lane] + xq2;
            float go = gatesA[wid * GPAD + 96 + lane] + gatesB[wid * GPAD + 96 + lane] + xq3;
            float si = 0.5f * tanha(0.5f * gi) + 0.5f;
            float sf = 0.5f * tanha(0.5f * gf) + 0.5f;
            float so = 0.5f * tanha(0.5f * go) + 0.5f;
            cst = sf * cst + si * tanha(gg);
            h = so * tanha(cst);
        }
        __nv_bfloat16 hb16 = __float2bfloat16(h);
        g_hsb[(size_t)(t * BB + bg * 16 + wid) * (2 * HH) + dir * HH + j0 + lane] = hb16;

        if (s + 1 < TT) {
            unsigned hb = (unsigned)(*(unsigned short*)&hb16);
            unsigned o1 = __shfl_xor_sync(0xffffffffu, hb, 1);
            unsigned p32 = (lane & 1) ? ((hb << 16) | o1) : ((o1 << 16) | hb);
            unsigned o2 = __shfl_xor_sync(0xffffffffu, p32, 2);
            unsigned lo = (lane & 2) ? o2 : p32;
            unsigned hi = (lane & 2) ? p32 : o2;
            unsigned lo2 = __shfl_xor_sync(0xffffffffu, lo, 4);
            unsigned hi2 = __shfl_xor_sync(0xffffffffu, hi, 4);
            unsigned r0 = (lane & 4) ? lo2 : lo;
            unsigned r1 = (lane & 4) ? hi2 : hi;
            unsigned r2 = (lane & 4) ? lo : lo2;
            unsigned r3 = (lane & 4) ? hi : hi2;
            unsigned off = (unsigned)((p ^ 1) * STG_PAR);
#pragma unroll
            for (int i = 0; i < 2; i++)
                asm volatile("st.shared::cluster.v4.b32 [%0], {%1,%2,%3,%4};"
                             :: "r"(pst[i] + off), "r"(r0), "r"(r1), "r"(r2), "r"(r3) : "memory");
            __syncthreads();
            if (wid == 0 && lane < 16)
                asm volatile("mbarrier.arrive.release.cluster.shared::cluster.b64 _, [%0];"
                             :: "r"(pmbar + (unsigned)((p ^ 1) * 8)) : "memory");
        }
    }

    asm volatile("barrier.cluster.arrive.aligned;" ::: "memory");
    asm volatile("barrier.cluster.wait.aligned;" ::: "memory");
}

// ------------------------- tag projection: bf16 mma GEMM -------------------------
#define TBK 64
#define TB_STRIDE 40
#define TA_STRIDE 72
#define TA_BUF (128 * TA_STRIDE)
#define TSMEM ((1024 * TB_STRIDE + 2 * TA_BUF) * 2)

__global__ __launch_bounds__(256) void k_tag(const float* __restrict__ Wtag,
                                             const float* __restrict__ btag)
{
    extern __shared__ char tsm[];
    __nv_bfloat16* Bt = (__nv_bfloat16*)tsm;
    __nv_bfloat16* As = Bt + 1024 * TB_STRIDE;

    int tid = threadIdx.x;
    int wid = tid >> 5;
    int lane = tid & 31;
    int m0 = blockIdx.x * 128;

    for (int idx = tid; idx < 1024 * 32; idx += 256) {
        int k = idx >> 5, n = idx & 31;
        float v = (n < KK) ? Wtag[k * KK + n] : 0.f;
        Bt[k * TB_STRIDE + n] = __float2bfloat16(v);
    }

    auto loadA = [&](int buf, int k0) {
        __nv_bfloat16* Ab = As + buf * TA_BUF;
#pragma unroll
        for (int j = 0; j < 4; j++) {
            int c = tid + j * 256;
            int r = c >> 3, q = c & 7;
            unsigned dst = smaddr(Ab + r * TA_STRIDE + q * 8);
            const __nv_bfloat16* src = g_hsb + (size_t)(m0 + r) * 1024 + k0 + q * 8;
            asm volatile("cp.async.cg.shared.global [%0], [%1], 16;\n" :: "r"(dst), "l"(src));
        }
    };

    loadA(0, 0);
    asm volatile("cp.async.commit_group;\n");
    __syncthreads();

    float acc[4][4];
#pragma unroll
    for (int i = 0; i < 4; i++)
#pragma unroll
        for (int j = 0; j < 4; j++) acc[i][j] = 0.f;

    for (int kt = 0; kt < 1024 / TBK; kt++) {
        int buf = kt & 1;
        if (kt + 1 < 1024 / TBK) {
            loadA(buf ^ 1, (kt + 1) * TBK);
            asm volatile("cp.async.commit_group;\n");
            asm volatile("cp.async.wait_group 1;\n");
        } else {
            asm volatile("cp.async.wait_group 0;\n");
        }
        __syncthreads();
        __nv_bfloat16* Ab = As + buf * TA_BUF;
#pragma unroll
        for (int ks = 0; ks < 4; ks++) {
            int k0 = ks * 16;
            int kabs = kt * TBK + k0;
            unsigned a[4];
            unsigned addr = smaddr(Ab + (wid * 16 + (lane & 15)) * TA_STRIDE + k0 + 8 * (lane >> 4));
            asm volatile("ldmatrix.sync.aligned.m8n8.x4.shared.b16 {%0,%1,%2,%3}, [%4];\n"
                         : "=r"(a[0]), "=r"(a[1]), "=r"(a[2]), "=r"(a[3]) : "r"(addr));
            unsigned b[2][4];
#pragma unroll
            for (int nj = 0; nj < 2; nj++) {
                unsigned baddr = smaddr(Bt + (kabs + (lane & 15)) * TB_STRIDE + nj * 16 + 8 * (lane >> 4));
                asm volatile("ldmatrix.sync.aligned.m8n8.x4.trans.shared.b16 {%0,%1,%2,%3}, [%4];\n"
                             : "=r"(b[nj][0]), "=r"(b[nj][1]), "=r"(b[nj][2]), "=r"(b[nj][3])
                             : "r"(baddr));
            }
#pragma unroll
            for (int ni = 0; ni < 4; ni++) {
                unsigned b0 = b[ni >> 1][(ni & 1) * 2];
                unsigned b1 = b[ni >> 1][(ni & 1) * 2 + 1];
                asm volatile(
                    "mma.sync.aligned.m16n8k16.row.col.f32.bf16.bf16.f32 "
                    "{%0,%1,%2,%3}, {%4,%5,%6,%7}, {%8,%9}, {%0,%1,%2,%3};\n"
                    : "+f"(acc[ni][0]), "+f"(acc[ni][1]), "+f"(acc[ni][2]), "+f"(acc[ni][3])
                    : "r"(a[0]), "r"(a[1]), "r"(a[2]), "r"(a[3]), "r"(b0), "r"(b1));
            }
        }
        __syncthreads();
    }

#pragma unroll
    for (int ni = 0; ni < 4; ni++) {
        int col = ni * 8 + (lane & 3) * 2;
#pragma unroll
        for (int half = 0; half < 2; half++) {
            int m = m0 + wid * 16 + (lane >> 2) + half * 8;
            int b = m & 31, t = m >> 5;
            float* fo = g_feats + ((size_t)b * TT + t) * KK;
            if (col < KK)     fo[col]     = acc[ni][half * 2]     + btag[col];
            if (col + 1 < KK) fo[col + 1] = acc[ni][half * 2 + 1] + btag[col + 1];
        }
    }
}

// ------------------------- CRF NLL (one warp per sentence) -------------------------
__global__ void k_crf(const float* __restrict__ trans, const int* __restrict__ tags,
                      float* __restrict__ out)
{
    int b = blockIdx.x;
    int lane = threadIdx.x;
    float trow[KK];
    int lr = (lane < KK) ? lane : 0;
#pragma unroll
    for (int p = 0; p < KK; p++) trow[p] = trans[lr * KK + p];
    float alpha = (lane == TSTART) ? 0.f : NEGV;
    const float* fb = g_feats + (size_t)b * TT * KK;
    for (int t = 0; t < TT; t++) {
        float emit = (lane < KK) ? fb[t * KK + lane] : 0.f;
        float v[KK];
        float vmax = -1e30f;
#pragma unroll
        for (int p = 0; p < KK; p++) {
            v[p] = __shfl_sync(0xffffffffu, alpha, p) + trow[p];
            vmax = fmaxf(vmax, v[p]);
        }
        float ssum = 0.f;
#pragma unroll
        for (int p = 0; p < KK; p++) ssum += __expf(v[p] - vmax);
        float na = vmax + __logf(ssum) + emit;
        alpha = (lane < KK) ? na : NEGV;
    }
    float v = (lane < KK) ? (alpha + trans[TSTOP * KK + lane]) : -1e30f;
    float m = v;
#pragma unroll
    for (int off = 16; off; off >>= 1) m = fmaxf(m, __shfl_xor_sync(0xffffffffu, m, off));
    float e = (lane < KK) ? __expf(v - m) : 0.f;
#pragma unroll
    for (int off = 16; off; off >>= 1) e += __shfl_xor_sync(0xffffffffu, e, off);
    float logz = m + __logf(e);
    const int* tg = tags + b * TT;
    float gold = 0.f;
    for (int j = lane; j < TT + 1; j += 32) {
        int prev = (j == 0) ? TSTART : tg[j - 1];
        int nxt  = (j < TT) ? tg[j] : TSTOP;
        gold += trans[nxt * KK + prev];
        if (j < TT) gold += fb[j * KK + tg[j]];
    }
#pragma unroll
    for (int off = 16; off; off >>= 1) gold += __shfl_xor_sync(0xffffffffu, gold, off);
    if (lane == 0) out[b] = logz - gold;
}

// ------------------------- launcher -------------------------
extern "C" void kernel_launch(void* const* d_in, const int* in_sizes, int n_in,
                              void* d_out, int out_size)
{
    const int*   ids   = (const int*)  d_in[0];
    const int*   tags  = (const int*)  d_in[1];
    const float* embed = (const float*)d_in[2];
    const float* Wihf  = (const float*)d_in[3];
    const float* Whhf  = (const float*)d_in[4];
    const float* bf    = (const float*)d_in[5];
    const float* Wihb  = (const float*)d_in[6];
    const float* Whhb  = (const float*)d_in[7];
    const float* bb    = (const float*)d_in[8];
    const float* Wtag  = (const float*)d_in[9];
    const float* btag  = (const float*)d_in[10];
    const float* trans = (const float*)d_in[11];
    float* out = (float*)d_out;

    cudaFuncSetAttribute(k_gemm, cudaFuncAttributeMaxDynamicSharedMemorySize, GSMEM);
    cudaFuncSetAttribute(k_tag,  cudaFuncAttributeMaxDynamicSharedMemorySize, TSMEM);
    cudaFuncSetAttribute(k_lstm2, cudaFuncAttributeMaxDynamicSharedMemorySize, LSM_BYTES);
    cudaFuncSetAttribute(k_lstm2, cudaFuncAttributeNonPortableClusterSizeAllowed, 1);

    {
        size_t nx = (size_t)MTOT * (DIN / 4);
        k_castx<<<(unsigned)((nx + 255) / 256), 256>>>(embed, ids);
        size_t nwt = 2 * NW4 + 2 * NH4;
        k_castw<<<(unsigned)((nwt + 255) / 256), 256>>>(Wihf, Wihb, Whhf, Whhb);
    }
    k_gemm<<<dim3(32, MTOT / BM), 256, GSMEM>>>(bf, bb);
    k_lstm2<<<64, 512, LSM_BYTES>>>();
    k_tag<<<MTOT / 128, 256, TSMEM>>>(Wtag, btag);
    k_crf<<<BB, 32>>>(trans, tags, out);
}